// round 1
// baseline (speedup 1.0000x reference)
#include <cuda_runtime.h>
#include <cuda_bf16.h>
#include <cstdint>

#define B_SZ 4
#define L_SZ 1024
#define DM   1024
#define DI   2048
#define DS   16
#define DTR  64
#define NTOK (B_SZ * L_SZ)   // 4096

// ---------------- scratch (device globals; no allocation allowed) ----------
__device__ float g_normed[NTOK * DM];        // 16 MB
__device__ float g_xz[NTOK * 2 * DI];        // 64 MB
__device__ float g_xc[NTOK * DI];            // 32 MB
__device__ float g_dt[NTOK * DI];            // 32 MB
__device__ float g_dtT[NTOK * DI];           // 32 MB  [b, d, t]
__device__ float g_xcT[NTOK * DI];           // 32 MB  [b, d, t]
__device__ float g_Bm[NTOK * DS];
__device__ float g_Cm[NTOK * DS];
__device__ float g_yT[NTOK * DI];            // 32 MB  [b, d, t]
__device__ float g_y[NTOK * DI];             // 32 MB  [token, d]
__device__ unsigned char g_maskc[NTOK];

// ---------------- mask canonicalization ------------------------------------
// mask comes from jax bool; harness may store it as 1-byte bool or int32.
// Detect: if it is int32 (little endian 0/1), every high byte of the first 32
// words is 0. A ~90%-ones byte mask has ~0 probability of 96 zero bytes.
__global__ void mask_prep_kernel(const void* maskraw, int n) {
    __shared__ int isint;
    if (threadIdx.x == 0) {
        const unsigned char* p = (const unsigned char*)maskraw;
        int nz = 0;
        for (int i = 0; i < 32; i++) {
            nz += (p[i * 4 + 1] != 0);
            nz += (p[i * 4 + 2] != 0);
            nz += (p[i * 4 + 3] != 0);
        }
        isint = (nz == 0);
    }
    __syncthreads();
    int ii = isint;
    for (int i = threadIdx.x; i < n; i += blockDim.x) {
        unsigned char v;
        if (ii) v = (((const int*)maskraw)[i] != 0);
        else    v = (((const unsigned char*)maskraw)[i] != 0);
        g_maskc[i] = v;
    }
}

// ---------------- rmsnorm ---------------------------------------------------
__global__ __launch_bounds__(256) void rmsnorm_kernel(const float* __restrict__ x,
                                                      const float* __restrict__ w) {
    int m = blockIdx.x;
    const float* xr = x + (size_t)m * DM;
    float s = 0.f;
    for (int i = threadIdx.x; i < DM; i += 256) { float v = xr[i]; s += v * v; }
    __shared__ float red[8];
    for (int o = 16; o; o >>= 1) s += __shfl_xor_sync(0xffffffffu, s, o);
    if ((threadIdx.x & 31) == 0) red[threadIdx.x >> 5] = s;
    __syncthreads();
    if (threadIdx.x < 8) {
        float v = red[threadIdx.x];
        for (int o = 4; o; o >>= 1) v += __shfl_xor_sync(0xffu, v, o);
        if (threadIdx.x == 0) red[0] = v;
    }
    __syncthreads();
    float scale = rsqrtf(red[0] * (1.0f / DM) + 1e-6f);
    for (int i = threadIdx.x; i < DM; i += 256)
        g_normed[(size_t)m * DM + i] = xr[i] * scale * w[i];
}

// ---------------- fp32 SGEMM core: C[M,N] = A[M,K] * W[N,K]^T ---------------
// 128x128 block tile, BK=16, 256 threads, 8x8 microtile (4+4 split).
__device__ __forceinline__ void sgemm_body(const float* __restrict__ A,
                                           const float* __restrict__ W,
                                           float* __restrict__ C,
                                           int N, int K,
                                           const float* __restrict__ xres,
                                           int epilogue) {
    __shared__ float As[16][128];
    __shared__ float Bs[16][128];
    const int bx = blockIdx.x, by = blockIdx.y;
    const int tid = threadIdx.x;
    const int tx = tid & 15, ty = tid >> 4;

    float acc[8][8];
#pragma unroll
    for (int i = 0; i < 8; i++)
#pragma unroll
        for (int j = 0; j < 8; j++) acc[i][j] = 0.f;

    const float* Ab = A + (size_t)by * 128 * K;
    const float* Wb = W + (size_t)bx * 128 * K;

    for (int k0 = 0; k0 < K; k0 += 16) {
#pragma unroll
        for (int it = 0; it < 2; it++) {
            int idx = tid + it * 256;        // 0..511  (512 float4 per operand)
            int row = idx >> 2;              // 0..127
            int c4  = (idx & 3) * 4;         // 0,4,8,12
            float4 va = *(const float4*)(Ab + (size_t)row * K + k0 + c4);
            As[c4 + 0][row] = va.x; As[c4 + 1][row] = va.y;
            As[c4 + 2][row] = va.z; As[c4 + 3][row] = va.w;
            float4 vb = *(const float4*)(Wb + (size_t)row * K + k0 + c4);
            Bs[c4 + 0][row] = vb.x; Bs[c4 + 1][row] = vb.y;
            Bs[c4 + 2][row] = vb.z; Bs[c4 + 3][row] = vb.w;
        }
        __syncthreads();
#pragma unroll
        for (int k = 0; k < 16; k++) {
            float4 a0 = *(const float4*)(&As[k][ty * 4]);
            float4 a1 = *(const float4*)(&As[k][64 + ty * 4]);
            float4 b0 = *(const float4*)(&Bs[k][tx * 4]);
            float4 b1 = *(const float4*)(&Bs[k][64 + tx * 4]);
            float ra[8] = {a0.x, a0.y, a0.z, a0.w, a1.x, a1.y, a1.z, a1.w};
            float rb[8] = {b0.x, b0.y, b0.z, b0.w, b1.x, b1.y, b1.z, b1.w};
#pragma unroll
            for (int i = 0; i < 8; i++)
#pragma unroll
                for (int j = 0; j < 8; j++) acc[i][j] = fmaf(ra[i], rb[j], acc[i][j]);
        }
        __syncthreads();
    }

#pragma unroll
    for (int i = 0; i < 8; i++) {
        int m = by * 128 + ((i < 4) ? (ty * 4 + i) : (64 + ty * 4 + i - 4));
#pragma unroll
        for (int j = 0; j < 8; j++) {
            int n = bx * 128 + ((j < 4) ? (tx * 4 + j) : (64 + tx * 4 + j - 4));
            float v = acc[i][j];
            if (epilogue) {
                v = g_maskc[m] ? (xres[(size_t)m * N + n] + v) : 0.f;
            }
            C[(size_t)m * N + n] = v;
        }
    }
}

__global__ __launch_bounds__(256) void sgemm_inproj_kernel(const float* __restrict__ W) {
    sgemm_body(g_normed, W, g_xz, 2 * DI, DM, nullptr, 0);
}
__global__ __launch_bounds__(256) void sgemm_outproj_kernel(const float* __restrict__ W,
                                                            const float* __restrict__ x,
                                                            float* __restrict__ out) {
    sgemm_body(g_y, W, out, DM, DI, x, 1);
}

// ---------------- segmented causal conv + SiLU ------------------------------
__global__ __launch_bounds__(256) void conv_silu_kernel(const float* __restrict__ convw,
                                                        const float* __restrict__ convb) {
    int idx = blockIdx.x * 256 + threadIdx.x;   // NTOK*DI threads
    int c = idx & (DI - 1);
    int m = idx >> 11;
    int t = m & (L_SZ - 1);
    float acc = convb[c];
    if (g_maskc[m]) {
        acc += convw[c * 4 + 3] * g_xz[(size_t)m * (2 * DI) + c];
        if (t >= 1 && g_maskc[m - 1]) {
            acc += convw[c * 4 + 2] * g_xz[(size_t)(m - 1) * (2 * DI) + c];
            if (t >= 2 && g_maskc[m - 2]) {
                acc += convw[c * 4 + 1] * g_xz[(size_t)(m - 2) * (2 * DI) + c];
                if (t >= 3 && g_maskc[m - 3]) {
                    acc += convw[c * 4 + 0] * g_xz[(size_t)(m - 3) * (2 * DI) + c];
                }
            }
        }
    }
    float sg = 1.0f / (1.0f + __expf(-acc));
    g_xc[idx] = acc * sg;
}

// ---------------- fused x_proj + dt_proj + softplus (block per token) -------
__global__ __launch_bounds__(256) void xproj_dt_kernel(const float* __restrict__ xpw,
                                                       const float* __restrict__ dtw,
                                                       const float* __restrict__ dtb) {
    int m = blockIdx.x;
    __shared__ float sx[DI];
    __shared__ float sdt[DTR];
    const float* xr = g_xc + (size_t)m * DI;
    for (int i = threadIdx.x; i < DI; i += 256) sx[i] = xr[i];
    __syncthreads();

    if (threadIdx.x < DTR + 2 * DS) {           // 96 rows of x_proj_w
        int e = threadIdx.x;
        const float* wr = xpw + (size_t)e * DI;
        float a0 = 0.f, a1 = 0.f, a2 = 0.f, a3 = 0.f;
#pragma unroll 4
        for (int k = 0; k < DI; k += 4) {
            a0 = fmaf(sx[k + 0], wr[k + 0], a0);
            a1 = fmaf(sx[k + 1], wr[k + 1], a1);
            a2 = fmaf(sx[k + 2], wr[k + 2], a2);
            a3 = fmaf(sx[k + 3], wr[k + 3], a3);
        }
        float acc = (a0 + a1) + (a2 + a3);
        if (e < DTR)            sdt[e] = acc;
        else if (e < DTR + DS)  g_Bm[m * DS + (e - DTR)] = acc;
        else                    g_Cm[m * DS + (e - DTR - DS)] = acc;
    }
    __syncthreads();

    for (int d = threadIdx.x; d < DI; d += 256) {
        float acc = dtb[d];
        const float* wr = dtw + (size_t)d * DTR;
#pragma unroll
        for (int r = 0; r < DTR; r++) acc = fmaf(sdt[r], wr[r], acc);
        float sp = (acc > 20.f) ? acc : log1pf(__expf(acc));
        g_dt[(size_t)m * DI + d] = sp;
    }
}

// ---------------- 32x32 tiled transpose [b,t,d] -> [b,d,t] ------------------
__global__ void transpose_kernel(int which) {
    const float* in = which ? g_xc : g_dt;
    float* out      = which ? g_xcT : g_dtT;
    __shared__ float sh[32][33];
    int b = blockIdx.z;
    int d0 = blockIdx.x * 32, t0 = blockIdx.y * 32;
    int tx = threadIdx.x, ty = threadIdx.y;      // 32 x 8
#pragma unroll
    for (int i = 0; i < 4; i++) {
        int t = t0 + ty + i * 8;
        sh[ty + i * 8][tx] = in[((size_t)b * L_SZ + t) * DI + d0 + tx];
    }
    __syncthreads();
#pragma unroll
    for (int i = 0; i < 4; i++) {
        int d = d0 + ty + i * 8;
        out[((size_t)b * DI + d) * L_SZ + t0 + tx] = sh[tx][ty + i * 8];
    }
}

// ---------------- selective scan: 16 lanes per (b,d), one state per lane ----
__global__ __launch_bounds__(256) void scan_kernel(const float* __restrict__ A_log) {
    int gid = (blockIdx.x * 256 + threadIdx.x) >> 4;  // (b,d) group
    int s = threadIdx.x & 15;
    int b = gid >> 11;
    int d = gid & (DI - 1);
    float a = -__expf(A_log[d * DS + s]);
    const float* dtp = g_dtT + (size_t)(b * DI + d) * L_SZ;
    const float* xcp = g_xcT + (size_t)(b * DI + d) * L_SZ;
    const float* Bp  = g_Bm + (size_t)b * L_SZ * DS;
    const float* Cp  = g_Cm + (size_t)b * L_SZ * DS;
    const unsigned char* mp = g_maskc + b * L_SZ;
    float* yp = g_yT + (size_t)(b * DI + d) * L_SZ;

    float h = 0.f, ybuf = 0.f;
    for (int t = 0; t < L_SZ; t++) {
        float dt = dtp[t];
        float xc = xcp[t];
        float Bv = Bp[t * DS + s];
        float Cv = Cp[t * DS + s];
        float dA  = __expf(dt * a);
        float hn  = fmaf(dA, h, dt * Bv * xc);
        h = mp[t] ? hn : 0.f;
        float p = h * Cv;
        p += __shfl_xor_sync(0xffffffffu, p, 8);
        p += __shfl_xor_sync(0xffffffffu, p, 4);
        p += __shfl_xor_sync(0xffffffffu, p, 2);
        p += __shfl_xor_sync(0xffffffffu, p, 1);
        if ((t & 15) == s) ybuf = p;
        if ((t & 15) == 15) yp[(t & ~15) + s] = ybuf;   // 64B coalesced per group
    }
}

// ---------------- combine: y = (y_scan + D*x_c) * silu(z), back to [t,d] ----
__global__ void combine_kernel(const float* __restrict__ Dp) {
    __shared__ float sh[32][33];
    int b = blockIdx.z, d0 = blockIdx.x * 32, t0 = blockIdx.y * 32;
    int tx = threadIdx.x, ty = threadIdx.y;
#pragma unroll
    for (int i = 0; i < 4; i++) {
        int d = d0 + ty + i * 8;
        sh[ty + i * 8][tx] = g_yT[((size_t)b * DI + d) * L_SZ + t0 + tx];
    }
    __syncthreads();
#pragma unroll
    for (int i = 0; i < 4; i++) {
        int t = t0 + ty + i * 8;
        size_t m = (size_t)b * L_SZ + t;
        int d = d0 + tx;
        float yv  = sh[tx][ty + i * 8];
        float xcv = g_xc[m * DI + d];
        float zv  = g_xz[m * (2 * DI) + DI + d];
        float yy  = fmaf(Dp[d], xcv, yv);
        float sz  = zv / (1.0f + __expf(-zv));
        g_y[m * DI + d] = yy * sz;
    }
}

// ---------------- launch ----------------------------------------------------
extern "C" void kernel_launch(void* const* d_in, const int* in_sizes, int n_in,
                              void* d_out, int out_size) {
    const float* x        = (const float*)d_in[0];
    const void*  maskraw  = d_in[1];
    const float* rms_w    = (const float*)d_in[2];
    const float* in_proj  = (const float*)d_in[3];
    const float* conv_w   = (const float*)d_in[4];
    const float* conv_b   = (const float*)d_in[5];
    const float* x_proj   = (const float*)d_in[6];
    const float* dt_proj  = (const float*)d_in[7];
    const float* dt_b     = (const float*)d_in[8];
    const float* A_log    = (const float*)d_in[9];
    const float* Dvec     = (const float*)d_in[10];
    const float* out_proj = (const float*)d_in[11];
    float* out = (float*)d_out;

    mask_prep_kernel<<<1, 256>>>(maskraw, NTOK);
    rmsnorm_kernel<<<NTOK, 256>>>(x, rms_w);

    dim3 g1((2 * DI) / 128, NTOK / 128);           // 32 x 32
    sgemm_inproj_kernel<<<g1, 256>>>(in_proj);

    conv_silu_kernel<<<(NTOK * DI) / 256, 256>>>(conv_w, conv_b);
    xproj_dt_kernel<<<NTOK, 256>>>(x_proj, dt_proj, dt_b);

    dim3 tg(DI / 32, L_SZ / 32, B_SZ);
    dim3 tb(32, 8);
    transpose_kernel<<<tg, tb>>>(0);   // dt -> dtT
    transpose_kernel<<<tg, tb>>>(1);   // xc -> xcT

    scan_kernel<<<(B_SZ * DI * DS) / 256, 256>>>(A_log);

    combine_kernel<<<tg, tb>>>(Dvec);

    dim3 g2(DM / 128, NTOK / 128);                 // 8 x 32
    sgemm_outproj_kernel<<<g2, 256>>>(out_proj, x, out);
}

// round 3
// speedup vs baseline: 4.6722x; 4.6722x over previous
#include <cuda_runtime.h>
#include <cuda_bf16.h>
#include <cstdint>

#define B_SZ 4
#define L_SZ 1024
#define DM   1024
#define DI   2048
#define DS   16
#define DTR  64
#define NTOK (B_SZ * L_SZ)   // 4096

// ---------------- scratch (device globals; no allocation allowed) ----------
__device__ float g_xz[NTOK * 2 * DI];        // in_proj output [m][4096]
__device__ float g_xc[NTOK * DI];
__device__ float g_dt[NTOK * DI];
__device__ float g_dtT[NTOK * DI];           // [b, d, t]
__device__ float g_xcT[NTOK * DI];           // [b, d, t]
__device__ float g_Bm[NTOK * DS];
__device__ float g_Cm[NTOK * DS];
__device__ float g_yT[NTOK * DI];            // [b, d, t]
__device__ unsigned char g_maskc[NTOK];

// bf16 split-2 operands
__device__ __nv_bfloat16 g_nh[NTOK * DM];
__device__ __nv_bfloat16 g_nl[NTOK * DM];
__device__ __nv_bfloat16 g_wih[2 * DI * DM];
__device__ __nv_bfloat16 g_wil[2 * DI * DM];
__device__ __nv_bfloat16 g_yh[NTOK * DI];
__device__ __nv_bfloat16 g_yl[NTOK * DI];
__device__ __nv_bfloat16 g_woh[DM * DI];
__device__ __nv_bfloat16 g_wol[DM * DI];

// ======================= base-ISA helpers ==================================
__device__ __forceinline__ uint32_t smem_u32(const void* p) {
    uint32_t a;
    asm("{ .reg .u64 t; cvta.to.shared.u64 t, %1; cvt.u32.u64 %0, t; }" : "=r"(a) : "l"(p));
    return a;
}
__device__ __forceinline__ void cp_async16(uint32_t dst, const void* src) {
    asm volatile("cp.async.cg.shared.global [%0], [%1], 16;" :: "r"(dst), "l"(src) : "memory");
}
#define CP_COMMIT() asm volatile("cp.async.commit_group;" ::: "memory")
#define CP_WAIT1()  asm volatile("cp.async.wait_group 1;" ::: "memory")

__device__ __forceinline__ void ldsm4(uint32_t* r, uint32_t a) {
    asm volatile("ldmatrix.sync.aligned.m8n8.x4.shared.b16 {%0,%1,%2,%3}, [%4];"
        : "=r"(r[0]), "=r"(r[1]), "=r"(r[2]), "=r"(r[3]) : "r"(a));
}
__device__ __forceinline__ void mma16816(float* c, const uint32_t* a, const uint32_t* b) {
    asm volatile("mma.sync.aligned.m16n8k16.row.col.f32.bf16.bf16.f32 "
        "{%0,%1,%2,%3}, {%4,%5,%6,%7}, {%8,%9}, {%0,%1,%2,%3};"
        : "+f"(c[0]), "+f"(c[1]), "+f"(c[2]), "+f"(c[3])
        : "r"(a[0]), "r"(a[1]), "r"(a[2]), "r"(a[3]), "r"(b[0]), "r"(b[1]));
}

// ---------------- mask canonicalization ------------------------------------
__global__ void mask_prep_kernel(const void* maskraw, int n) {
    __shared__ int isint;
    if (threadIdx.x == 0) {
        const unsigned char* p = (const unsigned char*)maskraw;
        int nz = 0;
        for (int i = 0; i < 32; i++) {
            nz += (p[i * 4 + 1] != 0);
            nz += (p[i * 4 + 2] != 0);
            nz += (p[i * 4 + 3] != 0);
        }
        isint = (nz == 0);
    }
    __syncthreads();
    int ii = isint;
    for (int i = threadIdx.x; i < n; i += blockDim.x) {
        unsigned char v;
        if (ii) v = (((const int*)maskraw)[i] != 0);
        else    v = (((const unsigned char*)maskraw)[i] != 0);
        g_maskc[i] = v;
    }
}

// ---------------- fp32 -> bf16 hi/lo split ---------------------------------
__device__ __forceinline__ void split_body(const float* __restrict__ src,
                                           __nv_bfloat16* __restrict__ hi,
                                           __nv_bfloat16* __restrict__ lo, int n4) {
    int i = blockIdx.x * 256 + threadIdx.x;
    if (i < n4) {
        float4 v = ((const float4*)src)[i];
        __nv_bfloat16 h0 = __float2bfloat16(v.x);
        __nv_bfloat16 h1 = __float2bfloat16(v.y);
        __nv_bfloat16 h2 = __float2bfloat16(v.z);
        __nv_bfloat16 h3 = __float2bfloat16(v.w);
        __nv_bfloat162* hp = (__nv_bfloat162*)(hi + i * 4);
        __nv_bfloat162* lp = (__nv_bfloat162*)(lo + i * 4);
        hp[0] = __nv_bfloat162(h0, h1);
        hp[1] = __nv_bfloat162(h2, h3);
        lp[0] = __nv_bfloat162(__float2bfloat16(v.x - __bfloat162float(h0)),
                               __float2bfloat16(v.y - __bfloat162float(h1)));
        lp[1] = __nv_bfloat162(__float2bfloat16(v.z - __bfloat162float(h2)),
                               __float2bfloat16(v.w - __bfloat162float(h3)));
    }
}
__global__ __launch_bounds__(256) void split_win_kernel(const float* __restrict__ s) {
    split_body(s, g_wih, g_wil, (2 * DI * DM) / 4);
}
__global__ __launch_bounds__(256) void split_wout_kernel(const float* __restrict__ s) {
    split_body(s, g_woh, g_wol, (DM * DI) / 4);
}

// ---------------- rmsnorm (writes bf16 hi/lo) -------------------------------
__global__ __launch_bounds__(256) void rmsnorm_kernel(const float* __restrict__ x,
                                                      const float* __restrict__ w) {
    int m = blockIdx.x;
    const float* xr = x + (size_t)m * DM;
    float s = 0.f;
    for (int i = threadIdx.x; i < DM; i += 256) { float v = xr[i]; s += v * v; }
    __shared__ float red[8];
    for (int o = 16; o; o >>= 1) s += __shfl_xor_sync(0xffffffffu, s, o);
    if ((threadIdx.x & 31) == 0) red[threadIdx.x >> 5] = s;
    __syncthreads();
    if (threadIdx.x < 8) {
        float v = red[threadIdx.x];
        for (int o = 4; o; o >>= 1) v += __shfl_xor_sync(0xffu, v, o);
        if (threadIdx.x == 0) red[0] = v;
    }
    __syncthreads();
    float scale = rsqrtf(red[0] * (1.0f / DM) + 1e-6f);
    for (int i = threadIdx.x; i < DM; i += 256) {
        float v = xr[i] * scale * w[i];
        __nv_bfloat16 h = __float2bfloat16(v);
        g_nh[(size_t)m * DM + i] = h;
        g_nl[(size_t)m * DM + i] = __float2bfloat16(v - __bfloat162float(h));
    }
}

// =================== HMMA bf16-split GEMM ===================================
// C[M,N] = A[M,K]*W[N,K]^T with split-2 (Ah*Wh + Ah*Wl + Al*Wh), fp32 acc.
// 128x128 CTA tile, BK=32, 8 warps (2M x 4N), cp.async double buffer.
// SMEM rows padded to 80B -> conflict-free ldmatrix.
#define G_ROWB   80                       // bytes per smem row (32 bf16 + pad)
#define G_OPB    (128 * G_ROWB)           // 10240 B per operand tile
#define G_STAGEB (4 * G_OPB)              // 40960 B per stage
#define G_SMEM   (2 * G_STAGEB)           // 81920 B

__device__ __forceinline__ void gemm_hmma(const __nv_bfloat16* __restrict__ Ah,
                                          const __nv_bfloat16* __restrict__ Al,
                                          const __nv_bfloat16* __restrict__ Wh,
                                          const __nv_bfloat16* __restrict__ Wl,
                                          float* __restrict__ C, int N, int K,
                                          const float* __restrict__ xres, int epi) {
    extern __shared__ char gsm[];
    uint32_t sbase = smem_u32(gsm);
    const int tid = threadIdx.x;
    const int wid = tid >> 5, lane = tid & 31;
    const int wm = wid & 1, wn = wid >> 1;       // 2 x 4 warp grid
    const int bx = blockIdx.x, by = blockIdx.y;

    const __nv_bfloat16* srcs[4] = {
        Ah + (size_t)by * 128 * K, Al + (size_t)by * 128 * K,
        Wh + (size_t)bx * 128 * K, Wl + (size_t)bx * 128 * K };

    float acc[4][4][4];
#pragma unroll
    for (int i = 0; i < 4; i++)
#pragma unroll
        for (int j = 0; j < 4; j++)
#pragma unroll
            for (int q = 0; q < 4; q++) acc[i][j][q] = 0.f;

    // per-thread precomputed load mapping
    int lrow[8], lkg[8], lop[8];
#pragma unroll
    for (int p = 0; p < 8; p++) {
        int i = p * 256 + tid;
        lop[p] = i >> 9;
        int w = i & 511;
        lrow[p] = w >> 2;
        lkg[p] = w & 3;
    }

    auto load_stage = [&](int s, int k0) {
        uint32_t sb = sbase + s * G_STAGEB;
#pragma unroll
        for (int p = 0; p < 8; p++) {
            const __nv_bfloat16* src = srcs[lop[p]] + (size_t)lrow[p] * K + k0 + lkg[p] * 8;
            cp_async16(sb + lop[p] * G_OPB + lrow[p] * G_ROWB + lkg[p] * 16, src);
        }
        CP_COMMIT();
    };

    const int NC = K >> 5;
    load_stage(0, 0);
    load_stage(1, 32);

    // ldmatrix address components
    const int a_row = wm * 64 + (lane & 15);            // + mt*16
    const int a_cb  = (lane >> 4) * 16;                 // byte offset within row
    const int w_row = wn * 32 + (lane & 7) + ((lane >> 4) & 1) * 8;  // + p*16
    const int w_cb  = ((lane >> 3) & 1) * 16;

    for (int ch = 0; ch < NC; ++ch) {
        CP_WAIT1();
        __syncthreads();
        uint32_t st = sbase + (ch & 1) * G_STAGEB;
        uint32_t ah = st, al = st + G_OPB, wh = st + 2 * G_OPB, wl = st + 3 * G_OPB;
#pragma unroll
        for (int kk = 0; kk < 2; ++kk) {
            int kb = kk * 32;  // 16 bf16 = 32 bytes
            uint32_t fAh[4][4], fAl[4][4], fWh[4][2], fWl[4][2];
#pragma unroll
            for (int mt = 0; mt < 4; mt++) {
                uint32_t off = (uint32_t)(a_row + mt * 16) * G_ROWB + a_cb + kb;
                ldsm4(fAh[mt], ah + off);
                ldsm4(fAl[mt], al + off);
            }
#pragma unroll
            for (int p = 0; p < 2; p++) {
                uint32_t off = (uint32_t)(w_row + p * 16) * G_ROWB + w_cb + kb;
                uint32_t r[4];
                ldsm4(r, wh + off);
                fWh[p * 2][0] = r[0]; fWh[p * 2][1] = r[1];
                fWh[p * 2 + 1][0] = r[2]; fWh[p * 2 + 1][1] = r[3];
                ldsm4(r, wl + off);
                fWl[p * 2][0] = r[0]; fWl[p * 2][1] = r[1];
                fWl[p * 2 + 1][0] = r[2]; fWl[p * 2 + 1][1] = r[3];
            }
#pragma unroll
            for (int mt = 0; mt < 4; mt++)
#pragma unroll
                for (int nt = 0; nt < 4; nt++) {
                    mma16816(acc[mt][nt], fAh[mt], fWh[nt]);
                    mma16816(acc[mt][nt], fAh[mt], fWl[nt]);
                    mma16816(acc[mt][nt], fAl[mt], fWh[nt]);
                }
        }
        __syncthreads();
        if (ch + 2 < NC) load_stage(ch & 1, (ch + 2) * 32);
    }

    // epilogue: direct register -> gmem (float2 stores)
    const int r0 = by * 128 + wm * 64 + (lane >> 2);
    const int c0 = bx * 128 + wn * 32 + (lane & 3) * 2;
#pragma unroll
    for (int mt = 0; mt < 4; mt++) {
        int rowA = r0 + mt * 16, rowB = rowA + 8;
        int mA = epi ? (int)g_maskc[rowA] : 1;
        int mB = epi ? (int)g_maskc[rowB] : 1;
#pragma unroll
        for (int nt = 0; nt < 4; nt++) {
            int col = c0 + nt * 8;
            float2 vA = make_float2(acc[mt][nt][0], acc[mt][nt][1]);
            float2 vB = make_float2(acc[mt][nt][2], acc[mt][nt][3]);
            if (epi) {
                if (mA) {
                    float2 r = *(const float2*)(xres + (size_t)rowA * N + col);
                    vA.x += r.x; vA.y += r.y;
                } else vA = make_float2(0.f, 0.f);
                if (mB) {
                    float2 r = *(const float2*)(xres + (size_t)rowB * N + col);
                    vB.x += r.x; vB.y += r.y;
                } else vB = make_float2(0.f, 0.f);
            }
            *(float2*)(C + (size_t)rowA * N + col) = vA;
            *(float2*)(C + (size_t)rowB * N + col) = vB;
        }
    }
}

__global__ __launch_bounds__(256) void gemm_inproj_kernel() {
    gemm_hmma(g_nh, g_nl, g_wih, g_wil, g_xz, 2 * DI, DM, nullptr, 0);
}
__global__ __launch_bounds__(256) void gemm_outproj_kernel(const float* __restrict__ x,
                                                           float* __restrict__ out) {
    gemm_hmma(g_yh, g_yl, g_woh, g_wol, out, DM, DI, x, 1);
}

// ---------------- segmented causal conv + SiLU ------------------------------
__global__ __launch_bounds__(256) void conv_silu_kernel(const float* __restrict__ convw,
                                                        const float* __restrict__ convb) {
    int idx = blockIdx.x * 256 + threadIdx.x;
    int c = idx & (DI - 1);
    int m = idx >> 11;
    int t = m & (L_SZ - 1);
    float acc = convb[c];
    if (g_maskc[m]) {
        acc += convw[c * 4 + 3] * g_xz[(size_t)m * (2 * DI) + c];
        if (t >= 1 && g_maskc[m - 1]) {
            acc += convw[c * 4 + 2] * g_xz[(size_t)(m - 1) * (2 * DI) + c];
            if (t >= 2 && g_maskc[m - 2]) {
                acc += convw[c * 4 + 1] * g_xz[(size_t)(m - 2) * (2 * DI) + c];
                if (t >= 3 && g_maskc[m - 3]) {
                    acc += convw[c * 4 + 0] * g_xz[(size_t)(m - 3) * (2 * DI) + c];
                }
            }
        }
    }
    float sg = 1.0f / (1.0f + __expf(-acc));
    g_xc[idx] = acc * sg;
}

// ---------------- fused x_proj + dt_proj + softplus (8 tokens / block) ------
// dyn smem: sx[8][2048] (64KB) + sdt[8*64] + scratch
#define XP_SMEM (8 * 2048 * 4 + 8 * 64 * 4 + 96 * 8 * 4)
__global__ __launch_bounds__(256) void xproj_dt_kernel(const float* __restrict__ xpw,
                                                       const float* __restrict__ dtw,
                                                       const float* __restrict__ dtb) {
    extern __shared__ float xsm[];
    float* sx   = xsm;                 // [8][2048]
    float* sdt  = xsm + 8 * 2048;      // [8][64]  token-major
    float* sout = sdt + 8 * 64;        // [96][8]
    int m0 = blockIdx.x * 8;
    {   // load 8 tokens of x_c (contiguous)
        const float4* s = (const float4*)(g_xc + (size_t)m0 * DI);
        float4* d = (float4*)sx;
#pragma unroll
        for (int p = 0; p < 16; p++) d[p * 256 + threadIdx.x] = s[p * 256 + threadIdx.x];
    }
    __syncthreads();
    int wid = threadIdx.x >> 5, lid = threadIdx.x & 31;
    // 96 output rows, 2 per warp per pass, all 8 tokens at once
    for (int e0 = wid * 2; e0 < 96; e0 += 16) {
        const float* w0 = xpw + (size_t)e0 * DI;
        const float* w1 = xpw + (size_t)(e0 + 1) * DI;
        float a0[8], a1[8];
#pragma unroll
        for (int t = 0; t < 8; t++) { a0[t] = 0.f; a1[t] = 0.f; }
        for (int k = lid; k < DI; k += 32) {
            float wv0 = w0[k], wv1 = w1[k];
#pragma unroll
            for (int t = 0; t < 8; t++) {
                float xv = sx[t * 2048 + k];
                a0[t] = fmaf(wv0, xv, a0[t]);
                a1[t] = fmaf(wv1, xv, a1[t]);
            }
        }
#pragma unroll
        for (int t = 0; t < 8; t++) {
            for (int o = 16; o; o >>= 1) {
                a0[t] += __shfl_xor_sync(0xffffffffu, a0[t], o);
                a1[t] += __shfl_xor_sync(0xffffffffu, a1[t], o);
            }
        }
        if (lid == 0) {
#pragma unroll
            for (int t = 0; t < 8; t++) { sout[e0 * 8 + t] = a0[t]; sout[(e0 + 1) * 8 + t] = a1[t]; }
        }
    }
    __syncthreads();
    // scatter: dt_r -> sdt, B/C -> gmem
    for (int i = threadIdx.x; i < 96 * 8; i += 256) {
        int e = i >> 3, t = i & 7;
        float v = sout[i];
        if (e < DTR)      sdt[t * DTR + e] = v;
        else if (e < 80)  g_Bm[(m0 + t) * DS + (e - DTR)] = v;
        else              g_Cm[(m0 + t) * DS + (e - 80)] = v;
    }
    __syncthreads();
    // dt_proj + softplus for 8 tokens
    for (int d = threadIdx.x; d < DI; d += 256) {
        const float* wr = dtw + (size_t)d * DTR;
        float b = dtb[d];
        float a[8];
#pragma unroll
        for (int t = 0; t < 8; t++) a[t] = b;
#pragma unroll
        for (int r = 0; r < DTR; r++) {
            float wv = wr[r];
#pragma unroll
            for (int t = 0; t < 8; t++) a[t] = fmaf(sdt[t * DTR + r], wv, a[t]);
        }
#pragma unroll
        for (int t = 0; t < 8; t++) {
            float v = a[t];
            float sp = (v > 20.f) ? v : log1pf(__expf(v));
            g_dt[(size_t)(m0 + t) * DI + d] = sp;
        }
    }
}

// ---------------- 32x32 tiled transpose [b,t,d] -> [b,d,t] ------------------
__global__ void transpose_kernel(int which) {
    const float* in = which ? g_xc : g_dt;
    float* out      = which ? g_xcT : g_dtT;
    __shared__ float sh[32][33];
    int b = blockIdx.z;
    int d0 = blockIdx.x * 32, t0 = blockIdx.y * 32;
    int tx = threadIdx.x, ty = threadIdx.y;
#pragma unroll
    for (int i = 0; i < 4; i++) {
        int t = t0 + ty + i * 8;
        sh[ty + i * 8][tx] = in[((size_t)b * L_SZ + t) * DI + d0 + tx];
    }
    __syncthreads();
#pragma unroll
    for (int i = 0; i < 4; i++) {
        int d = d0 + ty + i * 8;
        out[((size_t)b * DI + d) * L_SZ + t0 + tx] = sh[tx][ty + i * 8];
    }
}

// ---------------- selective scan --------------------------------------------
__global__ __launch_bounds__(256) void scan_kernel(const float* __restrict__ A_log) {
    int gid = (blockIdx.x * 256 + threadIdx.x) >> 4;
    int s = threadIdx.x & 15;
    int b = gid >> 11;
    int d = gid & (DI - 1);
    float a = -__expf(A_log[d * DS + s]);
    const float* dtp = g_dtT + (size_t)(b * DI + d) * L_SZ;
    const float* xcp = g_xcT + (size_t)(b * DI + d) * L_SZ;
    const float* Bp  = g_Bm + (size_t)b * L_SZ * DS;
    const float* Cp  = g_Cm + (size_t)b * L_SZ * DS;
    const unsigned char* mp = g_maskc + b * L_SZ;
    float* yp = g_yT + (size_t)(b * DI + d) * L_SZ;

    float h = 0.f, ybuf = 0.f;
    for (int t = 0; t < L_SZ; t++) {
        float dt = dtp[t];
        float xc = xcp[t];
        float Bv = Bp[t * DS + s];
        float Cv = Cp[t * DS + s];
        float dA = __expf(dt * a);
        float hn = fmaf(dA, h, dt * Bv * xc);
        h = mp[t] ? hn : 0.f;
        float p = h * Cv;
        p += __shfl_xor_sync(0xffffffffu, p, 8);
        p += __shfl_xor_sync(0xffffffffu, p, 4);
        p += __shfl_xor_sync(0xffffffffu, p, 2);
        p += __shfl_xor_sync(0xffffffffu, p, 1);
        if ((t & 15) == s) ybuf = p;
        if ((t & 15) == 15) yp[(t & ~15) + s] = ybuf;
    }
}

// ---------------- combine: (y + D*x_c)*silu(z) -> bf16 hi/lo ----------------
__global__ void combine_kernel(const float* __restrict__ Dp) {
    __shared__ float sh[32][33];
    int b = blockIdx.z, d0 = blockIdx.x * 32, t0 = blockIdx.y * 32;
    int tx = threadIdx.x, ty = threadIdx.y;
#pragma unroll
    for (int i = 0; i < 4; i++) {
        int d = d0 + ty + i * 8;
        sh[ty + i * 8][tx] = g_yT[((size_t)b * DI + d) * L_SZ + t0 + tx];
    }
    __syncthreads();
#pragma unroll
    for (int i = 0; i < 4; i++) {
        int t = t0 + ty + i * 8;
        size_t m = (size_t)b * L_SZ + t;
        int d = d0 + tx;
        float yv  = sh[tx][ty + i * 8];
        float xcv = g_xc[m * DI + d];
        float zv  = g_xz[m * (2 * DI) + DI + d];
        float yy  = fmaf(Dp[d], xcv, yv);
        float sz  = zv / (1.0f + __expf(-zv));
        float res = yy * sz;
        __nv_bfloat16 h = __float2bfloat16(res);
        g_yh[m * DI + d] = h;
        g_yl[m * DI + d] = __float2bfloat16(res - __bfloat162float(h));
    }
}

// ---------------- launch ----------------------------------------------------
extern "C" void kernel_launch(void* const* d_in, const int* in_sizes, int n_in,
                              void* d_out, int out_size) {
    const float* x        = (const float*)d_in[0];
    const void*  maskraw  = d_in[1];
    const float* rms_w    = (const float*)d_in[2];
    const float* in_proj  = (const float*)d_in[3];
    const float* conv_w   = (const float*)d_in[4];
    const float* conv_b   = (const float*)d_in[5];
    const float* x_proj   = (const float*)d_in[6];
    const float* dt_proj  = (const float*)d_in[7];
    const float* dt_b     = (const float*)d_in[8];
    const float* A_log    = (const float*)d_in[9];
    const float* Dvec     = (const float*)d_in[10];
    const float* out_proj = (const float*)d_in[11];
    float* out = (float*)d_out;

    cudaFuncSetAttribute(gemm_inproj_kernel,  cudaFuncAttributeMaxDynamicSharedMemorySize, G_SMEM);
    cudaFuncSetAttribute(gemm_outproj_kernel, cudaFuncAttributeMaxDynamicSharedMemorySize, G_SMEM);
    cudaFuncSetAttribute(xproj_dt_kernel,     cudaFuncAttributeMaxDynamicSharedMemorySize, XP_SMEM);

    mask_prep_kernel<<<1, 256>>>(maskraw, NTOK);
    rmsnorm_kernel<<<NTOK, 256>>>(x, rms_w);
    split_win_kernel<<<(2 * DI * DM / 4 + 255) / 256, 256>>>(in_proj);
    split_wout_kernel<<<(DM * DI / 4 + 255) / 256, 256>>>(out_proj);

    dim3 g1((2 * DI) / 128, NTOK / 128);           // 32 x 32
    gemm_inproj_kernel<<<g1, 256, G_SMEM>>>();

    conv_silu_kernel<<<(NTOK * DI) / 256, 256>>>(conv_w, conv_b);
    xproj_dt_kernel<<<NTOK / 8, 256, XP_SMEM>>>(x_proj, dt_proj, dt_b);

    dim3 tg(DI / 32, L_SZ / 32, B_SZ);
    dim3 tb(32, 8);
    transpose_kernel<<<tg, tb>>>(0);
    transpose_kernel<<<tg, tb>>>(1);

    scan_kernel<<<(B_SZ * DI * DS) / 256, 256>>>(A_log);

    combine_kernel<<<tg, tb>>>(Dvec);

    dim3 g2(DM / 128, NTOK / 128);                 // 8 x 32
    gemm_outproj_kernel<<<g2, 256, G_SMEM>>>(x, out);
}

// round 4
// speedup vs baseline: 5.0625x; 1.0835x over previous
#include <cuda_runtime.h>
#include <cuda_fp16.h>
#include <cuda_bf16.h>
#include <cstdint>

#define B_SZ 4
#define L_SZ 1024
#define DM   1024
#define DI   2048
#define DS   16
#define DTR  64
#define NTOK (B_SZ * L_SZ)   // 4096

// ---------------- scratch (device globals; no allocation allowed) ----------
__device__ float g_xz[NTOK * 2 * DI];        // in_proj output [m][4096]
__device__ float g_xc[NTOK * DI];
__device__ float g_dt[NTOK * DI];
__device__ float g_dtT[NTOK * DI];           // [b, d, t]
__device__ float g_xcT[NTOK * DI];           // [b, d, t]
__device__ float g_Bm[NTOK * DS];
__device__ float g_Cm[NTOK * DS];
__device__ float g_yT[NTOK * DI];            // [b, d, t]
__device__ unsigned char g_maskc[NTOK];

// fp16 split-2 activations (hi+lo), fp16 weights (hi only)
__device__ __half g_nh[NTOK * DM];
__device__ __half g_nl[NTOK * DM];
__device__ __half g_wih[2 * DI * DM];
__device__ __half g_yh[NTOK * DI];
__device__ __half g_yl[NTOK * DI];
__device__ __half g_woh[DM * DI];

// ======================= base-ISA helpers ==================================
__device__ __forceinline__ uint32_t smem_u32(const void* p) {
    uint32_t a;
    asm("{ .reg .u64 t; cvta.to.shared.u64 t, %1; cvt.u32.u64 %0, t; }" : "=r"(a) : "l"(p));
    return a;
}
__device__ __forceinline__ void cp_async16(uint32_t dst, const void* src) {
    asm volatile("cp.async.cg.shared.global [%0], [%1], 16;" :: "r"(dst), "l"(src) : "memory");
}
#define CP_COMMIT() asm volatile("cp.async.commit_group;" ::: "memory")
#define CP_WAIT1()  asm volatile("cp.async.wait_group 1;" ::: "memory")

__device__ __forceinline__ void ldsm4(uint32_t* r, uint32_t a) {
    asm volatile("ldmatrix.sync.aligned.m8n8.x4.shared.b16 {%0,%1,%2,%3}, [%4];"
        : "=r"(r[0]), "=r"(r[1]), "=r"(r[2]), "=r"(r[3]) : "r"(a));
}
__device__ __forceinline__ void mma16816h(float* c, const uint32_t* a, const uint32_t* b) {
    asm volatile("mma.sync.aligned.m16n8k16.row.col.f32.f16.f16.f32 "
        "{%0,%1,%2,%3}, {%4,%5,%6,%7}, {%8,%9}, {%0,%1,%2,%3};"
        : "+f"(c[0]), "+f"(c[1]), "+f"(c[2]), "+f"(c[3])
        : "r"(a[0]), "r"(a[1]), "r"(a[2]), "r"(a[3]), "r"(b[0]), "r"(b[1]));
}

// ---------------- mask canonicalization ------------------------------------
__global__ void mask_prep_kernel(const void* maskraw, int n) {
    __shared__ int isint;
    if (threadIdx.x == 0) {
        const unsigned char* p = (const unsigned char*)maskraw;
        int nz = 0;
        for (int i = 0; i < 32; i++) {
            nz += (p[i * 4 + 1] != 0);
            nz += (p[i * 4 + 2] != 0);
            nz += (p[i * 4 + 3] != 0);
        }
        isint = (nz == 0);
    }
    __syncthreads();
    int ii = isint;
    for (int i = threadIdx.x; i < n; i += blockDim.x) {
        unsigned char v;
        if (ii) v = (((const int*)maskraw)[i] != 0);
        else    v = (((const unsigned char*)maskraw)[i] != 0);
        g_maskc[i] = v;
    }
}

// ---------------- fp32 -> fp16 weight convert -------------------------------
__device__ __forceinline__ void cvt_body(const float* __restrict__ src,
                                         __half* __restrict__ dst, int n4) {
    int i = blockIdx.x * 256 + threadIdx.x;
    if (i < n4) {
        float4 v = ((const float4*)src)[i];
        __half2* hp = (__half2*)(dst + i * 4);
        hp[0] = __floats2half2_rn(v.x, v.y);
        hp[1] = __floats2half2_rn(v.z, v.w);
    }
}
__global__ __launch_bounds__(256) void cvt_win_kernel(const float* __restrict__ s) {
    cvt_body(s, g_wih, (2 * DI * DM) / 4);
}
__global__ __launch_bounds__(256) void cvt_wout_kernel(const float* __restrict__ s) {
    cvt_body(s, g_woh, (DM * DI) / 4);
}

// ---------------- rmsnorm (writes fp16 hi/lo) -------------------------------
__global__ __launch_bounds__(256) void rmsnorm_kernel(const float* __restrict__ x,
                                                      const float* __restrict__ w) {
    int m = blockIdx.x;
    const float* xr = x + (size_t)m * DM;
    float s = 0.f;
    for (int i = threadIdx.x; i < DM; i += 256) { float v = xr[i]; s += v * v; }
    __shared__ float red[8];
    for (int o = 16; o; o >>= 1) s += __shfl_xor_sync(0xffffffffu, s, o);
    if ((threadIdx.x & 31) == 0) red[threadIdx.x >> 5] = s;
    __syncthreads();
    if (threadIdx.x < 8) {
        float v = red[threadIdx.x];
        for (int o = 4; o; o >>= 1) v += __shfl_xor_sync(0xffu, v, o);
        if (threadIdx.x == 0) red[0] = v;
    }
    __syncthreads();
    float scale = rsqrtf(red[0] * (1.0f / DM) + 1e-6f);
    for (int i = threadIdx.x; i < DM; i += 256) {
        float v = xr[i] * scale * w[i];
        __half h = __float2half_rn(v);
        g_nh[(size_t)m * DM + i] = h;
        g_nl[(size_t)m * DM + i] = __float2half_rn(v - __half2float(h));
    }
}

// =================== HMMA fp16 split-2 GEMM =================================
// C[M,N] = A[M,K]*W[N,K]^T with A = Ah + Al (fp16 split), W fp16.
// 2 products: Ah*W + Al*W, fp32 acc. 128x128 CTA tile, BK=32, 8 warps (2Mx4N),
// cp.async double buffer, 80B-padded rows (conflict-free ldmatrix).
#define G_ROWB   80
#define G_OPB    (128 * G_ROWB)           // 10240 B per operand tile
#define G_STAGEB (3 * G_OPB)              // 30720 B per stage
#define G_SMEM   (2 * G_STAGEB)           // 61440 B

__device__ __forceinline__ void gemm_hmma(const __half* __restrict__ Ah,
                                          const __half* __restrict__ Al,
                                          const __half* __restrict__ Wh,
                                          float* __restrict__ C, int N, int K,
                                          const float* __restrict__ xres, int epi) {
    extern __shared__ char gsm[];
    uint32_t sbase = smem_u32(gsm);
    const int tid = threadIdx.x;
    const int wid = tid >> 5, lane = tid & 31;
    const int wm = wid & 1, wn = wid >> 1;
    const int bx = blockIdx.x, by = blockIdx.y;

    const __half* srcs[3] = {
        Ah + (size_t)by * 128 * K, Al + (size_t)by * 128 * K,
        Wh + (size_t)bx * 128 * K };

    float acc[4][4][4];
#pragma unroll
    for (int i = 0; i < 4; i++)
#pragma unroll
        for (int j = 0; j < 4; j++)
#pragma unroll
            for (int q = 0; q < 4; q++) acc[i][j][q] = 0.f;

    int lrow[6], lkg[6], lop[6];
#pragma unroll
    for (int p = 0; p < 6; p++) {
        int i = p * 256 + tid;        // 0..1535 (3 ops x 512 float4)
        lop[p] = i >> 9;
        int w = i & 511;
        lrow[p] = w >> 2;
        lkg[p] = w & 3;
    }

    auto load_stage = [&](int s, int k0) {
        uint32_t sb = sbase + s * G_STAGEB;
#pragma unroll
        for (int p = 0; p < 6; p++) {
            const __half* src = srcs[lop[p]] + (size_t)lrow[p] * K + k0 + lkg[p] * 8;
            cp_async16(sb + lop[p] * G_OPB + lrow[p] * G_ROWB + lkg[p] * 16, src);
        }
        CP_COMMIT();
    };

    const int NC = K >> 5;
    load_stage(0, 0);
    load_stage(1, 32);

    const int a_row = wm * 64 + (lane & 15);
    const int a_cb  = (lane >> 4) * 16;
    const int w_row = wn * 32 + (lane & 7) + ((lane >> 4) & 1) * 8;
    const int w_cb  = ((lane >> 3) & 1) * 16;

    for (int ch = 0; ch < NC; ++ch) {
        CP_WAIT1();
        __syncthreads();
        uint32_t st = sbase + (ch & 1) * G_STAGEB;
        uint32_t ah = st, al = st + G_OPB, wh = st + 2 * G_OPB;
#pragma unroll
        for (int kk = 0; kk < 2; ++kk) {
            int kb = kk * 32;
            uint32_t fAh[4][4], fAl[4][4], fW[4][2];
#pragma unroll
            for (int mt = 0; mt < 4; mt++) {
                uint32_t off = (uint32_t)(a_row + mt * 16) * G_ROWB + a_cb + kb;
                ldsm4(fAh[mt], ah + off);
                ldsm4(fAl[mt], al + off);
            }
#pragma unroll
            for (int p = 0; p < 2; p++) {
                uint32_t off = (uint32_t)(w_row + p * 16) * G_ROWB + w_cb + kb;
                uint32_t r[4];
                ldsm4(r, wh + off);
                fW[p * 2][0] = r[0]; fW[p * 2][1] = r[1];
                fW[p * 2 + 1][0] = r[2]; fW[p * 2 + 1][1] = r[3];
            }
#pragma unroll
            for (int mt = 0; mt < 4; mt++)
#pragma unroll
                for (int nt = 0; nt < 4; nt++) {
                    mma16816h(acc[mt][nt], fAh[mt], fW[nt]);
                    mma16816h(acc[mt][nt], fAl[mt], fW[nt]);
                }
        }
        __syncthreads();
        if (ch + 2 < NC) load_stage(ch & 1, (ch + 2) * 32);
    }

    const int r0 = by * 128 + wm * 64 + (lane >> 2);
    const int c0 = bx * 128 + wn * 32 + (lane & 3) * 2;
#pragma unroll
    for (int mt = 0; mt < 4; mt++) {
        int rowA = r0 + mt * 16, rowB = rowA + 8;
        int mA = epi ? (int)g_maskc[rowA] : 1;
        int mB = epi ? (int)g_maskc[rowB] : 1;
#pragma unroll
        for (int nt = 0; nt < 4; nt++) {
            int col = c0 + nt * 8;
            float2 vA = make_float2(acc[mt][nt][0], acc[mt][nt][1]);
            float2 vB = make_float2(acc[mt][nt][2], acc[mt][nt][3]);
            if (epi) {
                if (mA) {
                    float2 r = *(const float2*)(xres + (size_t)rowA * N + col);
                    vA.x += r.x; vA.y += r.y;
                } else vA = make_float2(0.f, 0.f);
                if (mB) {
                    float2 r = *(const float2*)(xres + (size_t)rowB * N + col);
                    vB.x += r.x; vB.y += r.y;
                } else vB = make_float2(0.f, 0.f);
            }
            *(float2*)(C + (size_t)rowA * N + col) = vA;
            *(float2*)(C + (size_t)rowB * N + col) = vB;
        }
    }
}

__global__ __launch_bounds__(256) void gemm_inproj_kernel() {
    gemm_hmma(g_nh, g_nl, g_wih, g_xz, 2 * DI, DM, nullptr, 0);
}
__global__ __launch_bounds__(256) void gemm_outproj_kernel(const float* __restrict__ x,
                                                           float* __restrict__ out) {
    gemm_hmma(g_yh, g_yl, g_woh, out, DM, DI, x, 1);
}

// ---------------- segmented causal conv + SiLU ------------------------------
__global__ __launch_bounds__(256) void conv_silu_kernel(const float* __restrict__ convw,
                                                        const float* __restrict__ convb) {
    int idx = blockIdx.x * 256 + threadIdx.x;
    int c = idx & (DI - 1);
    int m = idx >> 11;
    int t = m & (L_SZ - 1);
    float acc = convb[c];
    if (g_maskc[m]) {
        acc += convw[c * 4 + 3] * g_xz[(size_t)m * (2 * DI) + c];
        if (t >= 1 && g_maskc[m - 1]) {
            acc += convw[c * 4 + 2] * g_xz[(size_t)(m - 1) * (2 * DI) + c];
            if (t >= 2 && g_maskc[m - 2]) {
                acc += convw[c * 4 + 1] * g_xz[(size_t)(m - 2) * (2 * DI) + c];
                if (t >= 3 && g_maskc[m - 3]) {
                    acc += convw[c * 4 + 0] * g_xz[(size_t)(m - 3) * (2 * DI) + c];
                }
            }
        }
    }
    float sg = 1.0f / (1.0f + __expf(-acc));
    g_xc[idx] = acc * sg;
}

// ---------------- fused x_proj + dt_proj + softplus (8 tokens / block) ------
#define XP_SMEM (8 * 2048 * 4 + 8 * 64 * 4 + 96 * 8 * 4)
__global__ __launch_bounds__(256) void xproj_dt_kernel(const float* __restrict__ xpw,
                                                       const float* __restrict__ dtw,
                                                       const float* __restrict__ dtb) {
    extern __shared__ float xsm[];
    float* sx   = xsm;
    float* sdt  = xsm + 8 * 2048;
    float* sout = sdt + 8 * 64;
    int m0 = blockIdx.x * 8;
    {
        const float4* s = (const float4*)(g_xc + (size_t)m0 * DI);
        float4* d = (float4*)sx;
#pragma unroll
        for (int p = 0; p < 16; p++) d[p * 256 + threadIdx.x] = s[p * 256 + threadIdx.x];
    }
    __syncthreads();
    int wid = threadIdx.x >> 5, lid = threadIdx.x & 31;
    for (int e0 = wid * 2; e0 < 96; e0 += 16) {
        const float* w0 = xpw + (size_t)e0 * DI;
        const float* w1 = xpw + (size_t)(e0 + 1) * DI;
        float a0[8], a1[8];
#pragma unroll
        for (int t = 0; t < 8; t++) { a0[t] = 0.f; a1[t] = 0.f; }
        for (int k = lid; k < DI; k += 32) {
            float wv0 = w0[k], wv1 = w1[k];
#pragma unroll
            for (int t = 0; t < 8; t++) {
                float xv = sx[t * 2048 + k];
                a0[t] = fmaf(wv0, xv, a0[t]);
                a1[t] = fmaf(wv1, xv, a1[t]);
            }
        }
#pragma unroll
        for (int t = 0; t < 8; t++) {
            for (int o = 16; o; o >>= 1) {
                a0[t] += __shfl_xor_sync(0xffffffffu, a0[t], o);
                a1[t] += __shfl_xor_sync(0xffffffffu, a1[t], o);
            }
        }
        if (lid == 0) {
#pragma unroll
            for (int t = 0; t < 8; t++) { sout[e0 * 8 + t] = a0[t]; sout[(e0 + 1) * 8 + t] = a1[t]; }
        }
    }
    __syncthreads();
    for (int i = threadIdx.x; i < 96 * 8; i += 256) {
        int e = i >> 3, t = i & 7;
        float v = sout[i];
        if (e < DTR)      sdt[t * DTR + e] = v;
        else if (e < 80)  g_Bm[(m0 + t) * DS + (e - DTR)] = v;
        else              g_Cm[(m0 + t) * DS + (e - 80)] = v;
    }
    __syncthreads();
    for (int d = threadIdx.x; d < DI; d += 256) {
        const float* wr = dtw + (size_t)d * DTR;
        float b = dtb[d];
        float a[8];
#pragma unroll
        for (int t = 0; t < 8; t++) a[t] = b;
#pragma unroll
        for (int r = 0; r < DTR; r++) {
            float wv = wr[r];
#pragma unroll
            for (int t = 0; t < 8; t++) a[t] = fmaf(sdt[t * DTR + r], wv, a[t]);
        }
#pragma unroll
        for (int t = 0; t < 8; t++) {
            float v = a[t];
            float sp = (v > 20.f) ? v : log1pf(__expf(v));
            g_dt[(size_t)(m0 + t) * DI + d] = sp;
        }
    }
}

// ---------------- 32x32 tiled transpose [b,t,d] -> [b,d,t] ------------------
__global__ void transpose_kernel(int which) {
    const float* in = which ? g_xc : g_dt;
    float* out      = which ? g_xcT : g_dtT;
    __shared__ float sh[32][33];
    int b = blockIdx.z;
    int d0 = blockIdx.x * 32, t0 = blockIdx.y * 32;
    int tx = threadIdx.x, ty = threadIdx.y;
#pragma unroll
    for (int i = 0; i < 4; i++) {
        int t = t0 + ty + i * 8;
        sh[ty + i * 8][tx] = in[((size_t)b * L_SZ + t) * DI + d0 + tx];
    }
    __syncthreads();
#pragma unroll
    for (int i = 0; i < 4; i++) {
        int d = d0 + ty + i * 8;
        out[((size_t)b * DI + d) * L_SZ + t0 + tx] = sh[tx][ty + i * 8];
    }
}

// ---------------- selective scan --------------------------------------------
__global__ __launch_bounds__(256) void scan_kernel(const float* __restrict__ A_log) {
    int gid = (blockIdx.x * 256 + threadIdx.x) >> 4;
    int s = threadIdx.x & 15;
    int b = gid >> 11;
    int d = gid & (DI - 1);
    float a = -__expf(A_log[d * DS + s]);
    const float* dtp = g_dtT + (size_t)(b * DI + d) * L_SZ;
    const float* xcp = g_xcT + (size_t)(b * DI + d) * L_SZ;
    const float* Bp  = g_Bm + (size_t)b * L_SZ * DS;
    const float* Cp  = g_Cm + (size_t)b * L_SZ * DS;
    const unsigned char* mp = g_maskc + b * L_SZ;
    float* yp = g_yT + (size_t)(b * DI + d) * L_SZ;

    float h = 0.f, ybuf = 0.f;
    for (int t = 0; t < L_SZ; t++) {
        float dt = dtp[t];
        float xc = xcp[t];
        float Bv = Bp[t * DS + s];
        float Cv = Cp[t * DS + s];
        float dA = __expf(dt * a);
        float hn = fmaf(dA, h, dt * Bv * xc);
        h = mp[t] ? hn : 0.f;
        float p = h * Cv;
        p += __shfl_xor_sync(0xffffffffu, p, 8);
        p += __shfl_xor_sync(0xffffffffu, p, 4);
        p += __shfl_xor_sync(0xffffffffu, p, 2);
        p += __shfl_xor_sync(0xffffffffu, p, 1);
        if ((t & 15) == s) ybuf = p;
        if ((t & 15) == 15) yp[(t & ~15) + s] = ybuf;
    }
}

// ---------------- combine: (y + D*x_c)*silu(z) -> fp16 hi/lo ----------------
__global__ void combine_kernel(const float* __restrict__ Dp) {
    __shared__ float sh[32][33];
    int b = blockIdx.z, d0 = blockIdx.x * 32, t0 = blockIdx.y * 32;
    int tx = threadIdx.x, ty = threadIdx.y;
#pragma unroll
    for (int i = 0; i < 4; i++) {
        int d = d0 + ty + i * 8;
        sh[ty + i * 8][tx] = g_yT[((size_t)b * DI + d) * L_SZ + t0 + tx];
    }
    __syncthreads();
#pragma unroll
    for (int i = 0; i < 4; i++) {
        int t = t0 + ty + i * 8;
        size_t m = (size_t)b * L_SZ + t;
        int d = d0 + tx;
        float yv  = sh[tx][ty + i * 8];
        float xcv = g_xc[m * DI + d];
        float zv  = g_xz[m * (2 * DI) + DI + d];
        float yy  = fmaf(Dp[d], xcv, yv);
        float sz  = zv / (1.0f + __expf(-zv));
        float res = yy * sz;
        __half h = __float2half_rn(res);
        g_yh[m * DI + d] = h;
        g_yl[m * DI + d] = __float2half_rn(res - __half2float(h));
    }
}

// ---------------- launch ----------------------------------------------------
extern "C" void kernel_launch(void* const* d_in, const int* in_sizes, int n_in,
                              void* d_out, int out_size) {
    const float* x        = (const float*)d_in[0];
    const void*  maskraw  = d_in[1];
    const float* rms_w    = (const float*)d_in[2];
    const float* in_proj  = (const float*)d_in[3];
    const float* conv_w   = (const float*)d_in[4];
    const float* conv_b   = (const float*)d_in[5];
    const float* x_proj   = (const float*)d_in[6];
    const float* dt_proj  = (const float*)d_in[7];
    const float* dt_b     = (const float*)d_in[8];
    const float* A_log    = (const float*)d_in[9];
    const float* Dvec     = (const float*)d_in[10];
    const float* out_proj = (const float*)d_in[11];
    float* out = (float*)d_out;

    cudaFuncSetAttribute(gemm_inproj_kernel,  cudaFuncAttributeMaxDynamicSharedMemorySize, G_SMEM);
    cudaFuncSetAttribute(gemm_outproj_kernel, cudaFuncAttributeMaxDynamicSharedMemorySize, G_SMEM);
    cudaFuncSetAttribute(xproj_dt_kernel,     cudaFuncAttributeMaxDynamicSharedMemorySize, XP_SMEM);

    // launch order puts gemm_inproj in the ncu-captured slot (4th launch)
    mask_prep_kernel<<<1, 256>>>(maskraw, NTOK);
    rmsnorm_kernel<<<NTOK, 256>>>(x, rms_w);
    cvt_win_kernel<<<(2 * DI * DM / 4 + 255) / 256, 256>>>(in_proj);

    dim3 g1((2 * DI) / 128, NTOK / 128);           // 32 x 32
    gemm_inproj_kernel<<<g1, 256, G_SMEM>>>();

    cvt_wout_kernel<<<(DM * DI / 4 + 255) / 256, 256>>>(out_proj);
    conv_silu_kernel<<<(NTOK * DI) / 256, 256>>>(conv_w, conv_b);
    xproj_dt_kernel<<<NTOK / 8, 256, XP_SMEM>>>(x_proj, dt_proj, dt_b);

    dim3 tg(DI / 32, L_SZ / 32, B_SZ);
    dim3 tb(32, 8);
    transpose_kernel<<<tg, tb>>>(0);
    transpose_kernel<<<tg, tb>>>(1);

    scan_kernel<<<(B_SZ * DI * DS) / 256, 256>>>(A_log);

    combine_kernel<<<tg, tb>>>(Dvec);

    dim3 g2(DM / 128, NTOK / 128);                 // 8 x 32
    gemm_outproj_kernel<<<g2, 256, G_SMEM>>>(x, out);
}